// round 16
// baseline (speedup 1.0000x reference)
#include <cuda_runtime.h>
#include <cuda_bf16.h>
#include <cuda_fp16.h>
#include <cstdint>

#define BB 16
#define LL 512
#define DD 1024
#define HH 16
#define FF 4096
#define CC 10
#define NLAYER 6

typedef __half f16;

__device__ f16 g_xhi[BB * LL * DD];
__device__ f16 g_xlo[BB * LL * DD];
__device__ f16 g_tmph[BB * LL * DD];
__device__ f16 g_qkvp[2 * LL * 3 * DD];
__device__ f16 g_qkvh[LL * 3 * DD];
__device__ f16 g_ohi[LL * DD];
__device__ f16 g_src2h[4 * LL * DD];
__device__ float g_bff[DD];
__device__ float g_bffpart[32 * DD];
__device__ float g_bqkv[3 * DD];
__device__ float g_pooled[BB * DD];
__device__ int g_ids64;
__device__ f16 g_wqkvT[3 * DD * DD];
__device__ f16 g_woT[DD * DD];
__device__ f16 g_WffT[DD * DD];
__device__ f16 g_w1h[DD * FF];
__device__ f16 g_w2T[DD * FF];

__device__ __forceinline__ void f2hl(float v, f16& h, f16& l) {
    h = __float2half(v);
    l = __float2half(v - __half2float(h));
}
__device__ __forceinline__ float warpSum(float v) {
    #pragma unroll
    for (int o = 16; o > 0; o >>= 1) v += __shfl_xor_sync(0xffffffffu, v, o);
    return v;
}
__device__ __forceinline__ float blockSum(float v) {
    __shared__ float sm[32];
    int lane = threadIdx.x & 31, w = threadIdx.x >> 5;
    v = warpSum(v);
    if (lane == 0) sm[w] = v;
    __syncthreads();
    if (w == 0) {
        float x = (lane < (int)(blockDim.x >> 5)) ? sm[lane] : 0.f;
        x = warpSum(x);
        if (lane == 0) sm[0] = x;
    }
    __syncthreads();
    float r = sm[0];
    __syncthreads();
    return r;
}

__device__ __forceinline__ uint32_t s2u(const void* p) {
    uint32_t a;
    asm("{ .reg .u64 t; cvta.to.shared.u64 t, %1; cvt.u32.u64 %0, t; }" : "=r"(a) : "l"(p));
    return a;
}
__device__ __forceinline__ void cpa(uint32_t dst, const void* src) {
    asm volatile("cp.async.cg.shared.global [%0], [%1], 16;" :: "r"(dst), "l"(src));
}
__device__ __forceinline__ void cpcommit() { asm volatile("cp.async.commit_group;"); }
template <int N> __device__ __forceinline__ void cpwait() {
    asm volatile("cp.async.wait_group %0;" :: "n"(N));
}
__device__ __forceinline__ void ldmx4(uint32_t* r, uint32_t a) {
    asm volatile("ldmatrix.sync.aligned.m8n8.x4.shared.b16 {%0,%1,%2,%3}, [%4];"
                 : "=r"(r[0]), "=r"(r[1]), "=r"(r[2]), "=r"(r[3]) : "r"(a));
}
__device__ __forceinline__ void mmah(float* d, const uint32_t* a, const uint32_t* b) {
    asm volatile(
        "mma.sync.aligned.m16n8k16.row.col.f32.f16.f16.f32 "
        "{%0,%1,%2,%3}, {%4,%5,%6,%7}, {%8,%9}, {%0,%1,%2,%3};"
        : "+f"(d[0]), "+f"(d[1]), "+f"(d[2]), "+f"(d[3])
        : "r"(a[0]), "r"(a[1]), "r"(a[2]), "r"(a[3]), "r"(b[0]), "r"(b[1]));
}

#define PITCH 80

// C[M,N] = A @ B^T + bias ; fp16 operands; multi-stage cp.async, 1 barrier/iter.
template <int MT>
__global__ __launch_bounds__(MT * 2, (MT == 64) ? 4 : 2) void gemm_tc(
    const f16* __restrict__ A, const f16* __restrict__ B,
    const float* __restrict__ bias, float* __restrict__ C, f16* __restrict__ Ch,
    int Kiter, int Kstride, int N, int Czoff) {
    constexpr int THREADS = MT * 2;
    constexpr int OFS_B = MT * PITCH;
    constexpr int STB = (MT + 128) * PITCH;
    constexpr int NST = (MT == 128) ? 5 : 3;
    extern __shared__ char smem[];
    uint32_t sb = s2u(smem);
    const int t = threadIdx.x, lane = t & 31, wid = t >> 5;
    const int m0 = blockIdx.y * MT, n0 = blockIdx.x * 128;
    const int wr = wid >> 2, wc = wid & 3;
    const size_t kz = (size_t)blockIdx.z * Kiter;
    if (C) C += (size_t)blockIdx.z * Czoff;
    if (Ch) Ch += (size_t)blockIdx.z * Czoff;
    const int NKB = Kiter / 32;

    float acc[4][4][4];
    #pragma unroll
    for (int i = 0; i < 4; i++)
        #pragma unroll
        for (int j = 0; j < 4; j++)
            #pragma unroll
            for (int r = 0; r < 4; r++) acc[i][j][r] = 0.f;

    const uint32_t aoff = (uint32_t)((wr * 64 + (lane & 15)) * PITCH + ((lane >> 4) << 4));
    const int brow = wc * 32 + (lane & 7) + ((lane & 16) ? 8 : 0);
    const uint32_t boff = (uint32_t)(brow * PITCH + ((lane & 8) ? 16 : 0));

    auto load_stage = [&](int kb0, uint32_t base) {
        #pragma unroll
        for (int idx = t; idx < MT * 4; idx += THREADS) {
            int row = idx >> 2, c = idx & 3;
            uint32_t so = (uint32_t)(row * PITCH + c * 16);
            cpa(base + so, A + (size_t)(m0 + row) * Kstride + kz + kb0 + c * 8);
        }
        #pragma unroll
        for (int idx = t; idx < 512; idx += THREADS) {
            int row = idx >> 2, c = idx & 3;
            uint32_t so = (uint32_t)(row * PITCH + c * 16);
            cpa(base + OFS_B + so, B + (size_t)(n0 + row) * Kstride + kz + kb0 + c * 8);
        }
        cpcommit();
    };

    #pragma unroll
    for (int s = 0; s < NST - 1; s++)
        load_stage(s * 32, sb + (uint32_t)s * STB);

    for (int kb = 0; kb < NKB; kb++) {
        cpwait<NST - 2>();
        __syncthreads();
        uint32_t base = sb + (uint32_t)(kb % NST) * STB;
        #pragma unroll
        for (int ks = 0; ks < 2; ks++) {
            uint32_t kbyte = (uint32_t)(ks * 32);
            uint32_t ah[4][4], bh[2][4];
            #pragma unroll
            for (int mt = 0; mt < 4; mt++)
                ldmx4(ah[mt], base + aoff + (uint32_t)(mt * 16 * PITCH) + kbyte);
            #pragma unroll
            for (int ng = 0; ng < 2; ng++)
                ldmx4(bh[ng], base + OFS_B + boff + (uint32_t)(ng * 16 * PITCH) + kbyte);
            #pragma unroll
            for (int mt = 0; mt < 4; mt++)
                #pragma unroll
                for (int nt = 0; nt < 4; nt++)
                    mmah(acc[mt][nt], ah[mt], &bh[nt >> 1][(nt & 1) * 2]);
        }
        int nxt = kb + NST - 1;
        if (nxt < NKB)
            load_stage(nxt * 32, sb + (uint32_t)(nxt % NST) * STB);
        else
            cpcommit();
    }

    #pragma unroll
    for (int mt = 0; mt < 4; mt++) {
        int m = m0 + wr * 64 + mt * 16 + (lane >> 2);
        #pragma unroll
        for (int nt = 0; nt < 4; nt++) {
            int n = n0 + wc * 32 + nt * 8 + (lane & 3) * 2;
            float b0 = 0.f, b1 = 0.f;
            if (bias) { b0 = bias[n]; b1 = bias[n + 1]; }
            float v0 = acc[mt][nt][0] + b0, v1 = acc[mt][nt][1] + b1;
            float v2 = acc[mt][nt][2] + b0, v3 = acc[mt][nt][3] + b1;
            if (Ch) {
                *(__half2*)(Ch + (size_t)m * N + n) = __floats2half2_rn(v0, v1);
                *(__half2*)(Ch + (size_t)(m + 8) * N + n) = __floats2half2_rn(v2, v3);
            } else {
                *(float2*)(C + (size_t)m * N + n) = make_float2(v0, v1);
                *(float2*)(C + (size_t)(m + 8) * N + n) = make_float2(v2, v3);
            }
        }
    }
}

__global__ void detect_kernel(const void* ids) {
    const int* p = (const int*)ids;
    int nz = 0;
    for (int i = 0; i < 256; i += 2)
        if (p[i + 1] != 0) nz++;
    g_ids64 = (nz == 0) ? 1 : 0;
}
__global__ void embed_kernel(const void* ids, const float* __restrict__ emb,
                             const float* __restrict__ pe) {
    int row = blockIdx.x;
    int d = threadIdx.x * 4;
    long long id;
    if (g_ids64) id = ((const long long*)ids)[row];
    else         id = (long long)((const int*)ids)[row];
    int l = row & (LL - 1);
    float4 e = *(const float4*)(emb + (size_t)id * DD + d);
    float4 p = *(const float4*)(pe + (size_t)l * DD + d);
    float v[4] = {e.x * 32.f + p.x, e.y * 32.f + p.y, e.z * 32.f + p.z, e.w * 32.f + p.w};
    size_t base = (size_t)row * DD + d;
    #pragma unroll
    for (int j = 0; j < 4; j++) {
        f16 h, lo;
        f2hl(v[j], h, lo);
        g_xhi[base + j] = h;
        g_xlo[base + j] = lo;
    }
}
__global__ void tconv4(const float* __restrict__ wq, const float* __restrict__ wk,
                       const float* __restrict__ wv, const float* __restrict__ wo) {
    __shared__ float tl[32][33];
    int z = blockIdx.z;
    const float* in = (z == 0) ? wq : (z == 1) ? wk : (z == 2) ? wv : wo;
    f16* oh = (z == 3) ? g_woT : g_wqkvT + (size_t)z * DD * DD;
    float scale = (z == 0) ? 0.125f : 1.f;
    int n0 = blockIdx.x * 32, k0 = blockIdx.y * 32;
    int tx = threadIdx.x, ty = threadIdx.y;
    #pragma unroll
    for (int i = 0; i < 4; i++)
        tl[ty + i * 8][tx] = in[(size_t)(k0 + ty + i * 8) * DD + n0 + tx] * scale;
    __syncthreads();
    #pragma unroll
    for (int i = 0; i < 4; i++) {
        int nn = ty + i * 8;
        oh[(size_t)(n0 + nn) * DD + k0 + tx] = __float2half(tl[tx][nn]);
    }
}
__global__ void tconv(const float* __restrict__ in, f16* __restrict__ oh,
                      int R, int C) {
    __shared__ float tl[32][33];
    int n0 = blockIdx.x * 32, k0 = blockIdx.y * 32;
    int tx = threadIdx.x, ty = threadIdx.y;
    #pragma unroll
    for (int i = 0; i < 4; i++)
        tl[ty + i * 8][tx] = in[(size_t)(k0 + ty + i * 8) * C + n0 + tx];
    __syncthreads();
    #pragma unroll
    for (int i = 0; i < 4; i++) {
        int nn = ty + i * 8;
        oh[(size_t)(n0 + nn) * R + k0 + tx] = __float2half(tl[tx][nn]);
    }
}
__global__ void conv_h(const float* __restrict__ in, f16* __restrict__ oh) {
    size_t i = ((size_t)blockIdx.x * 256 + threadIdx.x) * 4;
    float4 v = *(const float4*)(in + i);
    oh[i + 0] = __float2half(v.x);
    oh[i + 1] = __float2half(v.y);
    oh[i + 2] = __float2half(v.z);
    oh[i + 3] = __float2half(v.w);
}
__global__ void concat_bias(const float* __restrict__ bq, const float* __restrict__ bk,
                            const float* __restrict__ bv) {
    int t = threadIdx.x, s = blockIdx.x;
    const float* src = (s == 0) ? bq : (s == 1) ? bk : bv;
    g_bqkv[s * DD + t] = src[t] * ((s == 0) ? 0.125f : 1.f);
}
__global__ __launch_bounds__(256) void bff_part(const float* __restrict__ b1,
                                                const float* __restrict__ w2) {
    int y = blockIdx.x, t = threadIdx.x;
    float s[4] = {0.f, 0.f, 0.f, 0.f};
    for (int f = y * 128; f < y * 128 + 128; f++) {
        float bv = b1[f];
        const float* wr = w2 + (size_t)f * DD;
        #pragma unroll
        for (int j = 0; j < 4; j++) s[j] = fmaf(bv, wr[t + j * 256], s[j]);
    }
    #pragma unroll
    for (int j = 0; j < 4; j++) g_bffpart[y * DD + t + j * 256] = s[j];
}
__global__ __launch_bounds__(256) void bff_reduce(const float* __restrict__ b2) {
    int d = blockIdx.x * 256 + threadIdx.x;
    float s = b2[d];
    for (int y = 0; y < 32; y++) s += g_bffpart[y * DD + d];
    g_bff[d] = s;
}

// combine QKV split-K partials + bias: qkvh = qkvp[0] + qkvp[1] + bqkv
__global__ __launch_bounds__(256) void qkv_comb() {
    size_t e = ((size_t)blockIdx.x * 256 + threadIdx.x) * 8;
    int n = (int)(e % (3 * DD));
    uint4 a = *(const uint4*)(g_qkvp + e);
    uint4 b = *(const uint4*)(g_qkvp + (size_t)LL * 3 * DD + e);
    float4 c0 = *(const float4*)(g_bqkv + n);
    float4 c1 = *(const float4*)(g_bqkv + n + 4);
    float bb[8] = {c0.x, c0.y, c0.z, c0.w, c1.x, c1.y, c1.z, c1.w};
    __half2* ap = (__half2*)&a;
    __half2* bp = (__half2*)&b;
    uint4 r;
    __half2* rp = (__half2*)&r;
    #pragma unroll
    for (int j = 0; j < 4; j++) {
        float x0 = __half2float(ap[j].x) + __half2float(bp[j].x) + bb[2 * j];
        float x1 = __half2float(ap[j].y) + __half2float(bp[j].y) + bb[2 * j + 1];
        rp[j] = __floats2half2_rn(x0, x1);
    }
    *(uint4*)(g_qkvh + e) = r;
}

// ---------------- HMMA flash attention, register-pipelined loads ----------------
__global__ __launch_bounds__(64) void flash_mma(const f16* __restrict__ qkv) {
    __shared__ __align__(16) char fsm[(32 + 64 + 64) * 144];
    const int OFQ = 0, OFK = 32 * 144, OFV = (32 + 64) * 144;
    uint32_t sb = s2u(fsm);
    int h = blockIdx.y, m0 = blockIdx.x * 32;
    int t = threadIdx.x, lane = t & 31, w = t >> 5;

    for (int i = t; i < 256; i += 64) {
        int r = i >> 3, c = i & 7;
        *(uint4*)(fsm + OFQ + r * 144 + c * 16) =
            *(const uint4*)(qkv + (size_t)(m0 + r) * (3 * DD) + h * 64 + c * 8);
    }
    __syncthreads();
    uint32_t qa[4][4];
    {
        uint32_t qoff = (uint32_t)((w * 16 + (lane & 15)) * 144 + ((lane >> 4) << 4));
        #pragma unroll
        for (int kt = 0; kt < 4; kt++) ldmx4(qa[kt], sb + OFQ + qoff + kt * 32);
    }

    const uint32_t brow = (uint32_t)((lane & 7) + ((lane & 16) ? 8 : 0));
    const uint32_t bcol = ((lane & 8) ? 16u : 0u);

    float m_run0 = -1e30f, m_run1 = -1e30f, l_run0 = 0.f, l_run1 = 0.f;
    float oacc[8][4];
    #pragma unroll
    for (int d = 0; d < 8; d++)
        #pragma unroll
        for (int r = 0; r < 4; r++) oacc[d][r] = 0.f;

    uint4 kreg[8];
    __half2 vreg[16][2];
    auto preload = [&](int kb) {
        #pragma unroll
        for (int i = 0; i < 8; i++) {
            int idx = t + i * 64;
            int r = idx >> 3, c = idx & 7;
            kreg[i] = *(const uint4*)(qkv + (size_t)(kb + r) * (3 * DD) + DD + h * 64 + c * 8);
        }
        #pragma unroll
        for (int i = 0; i < 16; i++) {
            int idx = t + i * 64;
            int key2 = (idx >> 5) * 2, d2 = idx & 31;
            const f16* vsrc = qkv + 2 * DD + h * 64 + 2 * d2;
            vreg[i][0] = *(const __half2*)(vsrc + (size_t)(kb + key2) * (3 * DD));
            vreg[i][1] = *(const __half2*)(vsrc + (size_t)(kb + key2 + 1) * (3 * DD));
        }
    };
    preload(0);

    for (int kb = 0; kb < LL; kb += 64) {
        __syncthreads();
        #pragma unroll
        for (int i = 0; i < 8; i++) {
            int idx = t + i * 64;
            int r = idx >> 3, c = idx & 7;
            *(uint4*)(fsm + OFK + r * 144 + c * 16) = kreg[i];
        }
        #pragma unroll
        for (int i = 0; i < 16; i++) {
            int idx = t + i * 64;
            int key2 = (idx >> 5) * 2, d2 = idx & 31;
            __half2 a = vreg[i][0], b = vreg[i][1];
            *(__half2*)(fsm + OFV + (2 * d2) * 144 + key2 * 2) = __halves2half2(a.x, b.x);
            *(__half2*)(fsm + OFV + (2 * d2 + 1) * 144 + key2 * 2) = __halves2half2(a.y, b.y);
        }
        __syncthreads();
        if (kb + 64 < LL) preload(kb + 64);

        float sacc[8][4];
        #pragma unroll
        for (int j = 0; j < 8; j++)
            #pragma unroll
            for (int r = 0; r < 4; r++) sacc[j][r] = 0.f;
        #pragma unroll
        for (int kt = 0; kt < 4; kt++) {
            #pragma unroll
            for (int ng = 0; ng < 4; ng++) {
                uint32_t kbf[4];
                ldmx4(kbf, sb + OFK + (uint32_t)(ng * 16) * 144 + brow * 144 + bcol + kt * 32);
                mmah(sacc[ng * 2 + 0], qa[kt], &kbf[0]);
                mmah(sacc[ng * 2 + 1], qa[kt], &kbf[2]);
            }
        }

        float ml0 = -1e30f, ml1 = -1e30f;
        #pragma unroll
        for (int j = 0; j < 8; j++) {
            ml0 = fmaxf(ml0, fmaxf(sacc[j][0], sacc[j][1]));
            ml1 = fmaxf(ml1, fmaxf(sacc[j][2], sacc[j][3]));
        }
        #pragma unroll
        for (int o = 1; o <= 2; o <<= 1) {
            ml0 = fmaxf(ml0, __shfl_xor_sync(0xffffffffu, ml0, o));
            ml1 = fmaxf(ml1, __shfl_xor_sync(0xffffffffu, ml1, o));
        }
        float mn0 = fmaxf(m_run0, ml0), mn1 = fmaxf(m_run1, ml1);
        float corr0 = __expf(m_run0 - mn0), corr1 = __expf(m_run1 - mn1);
        float rs0 = 0.f, rs1 = 0.f;
        uint32_t pfrag[4][4];
        #pragma unroll
        for (int kt = 0; kt < 4; kt++) {
            #pragma unroll
            for (int hh = 0; hh < 2; hh++) {
                int j = kt * 2 + hh;
                float p0 = __expf(sacc[j][0] - mn0), p1 = __expf(sacc[j][1] - mn0);
                float p2 = __expf(sacc[j][2] - mn1), p3 = __expf(sacc[j][3] - mn1);
                rs0 += p0 + p1;
                rs1 += p2 + p3;
                __half2 pa = __floats2half2_rn(p0, p1);
                __half2 pb = __floats2half2_rn(p2, p3);
                pfrag[kt][hh * 2 + 0] = *(uint32_t*)&pa;
                pfrag[kt][hh * 2 + 1] = *(uint32_t*)&pb;
            }
        }
        #pragma unroll
        for (int o = 1; o <= 2; o <<= 1) {
            rs0 += __shfl_xor_sync(0xffffffffu, rs0, o);
            rs1 += __shfl_xor_sync(0xffffffffu, rs1, o);
        }
        l_run0 = l_run0 * corr0 + rs0;
        l_run1 = l_run1 * corr1 + rs1;
        m_run0 = mn0;
        m_run1 = mn1;
        #pragma unroll
        for (int d = 0; d < 8; d++) {
            oacc[d][0] *= corr0; oacc[d][1] *= corr0;
            oacc[d][2] *= corr1; oacc[d][3] *= corr1;
        }
        #pragma unroll
        for (int kt = 0; kt < 4; kt++) {
            #pragma unroll
            for (int ng = 0; ng < 4; ng++) {
                uint32_t vb[4];
                ldmx4(vb, sb + OFV + (uint32_t)(ng * 16) * 144 + brow * 144 + bcol + kt * 32);
                mmah(oacc[ng * 2 + 0], pfrag[kt], &vb[0]);
                mmah(oacc[ng * 2 + 1], pfrag[kt], &vb[2]);
            }
        }
    }

    float inv0 = 1.f / l_run0, inv1 = 1.f / l_run1;
    int m = m0 + w * 16 + (lane >> 2);
    #pragma unroll
    for (int d = 0; d < 8; d++) {
        int n = h * 64 + d * 8 + 2 * (lane & 3);
        *(__half2*)(g_ohi + (size_t)m * DD + n) = __floats2half2_rn(oacc[d][0] * inv0, oacc[d][1] * inv0);
        *(__half2*)(g_ohi + (size_t)(m + 8) * DD + n) = __floats2half2_rn(oacc[d][2] * inv1, oacc[d][3] * inv1);
    }
}

// ---------------- warp-per-row residual + LayerNorm (two-pass, nadd partials) ----------------
__global__ __launch_bounds__(256) void add_ln(f16* __restrict__ xhi, f16* __restrict__ xlo,
                                              const f16* __restrict__ addh, int nadd,
                                              size_t astride,
                                              const float* __restrict__ cbias, int addMask,
                                              const float* __restrict__ g,
                                              const float* __restrict__ b) {
    int row = blockIdx.x * 8 + (threadIdx.x >> 5);
    int lane = threadIdx.x & 31;
    size_t base = (size_t)row * DD;
    size_t abase = (size_t)(row & addMask) * DD;
    float v[32];
    #pragma unroll
    for (int c = 0; c < 4; c++) {
        int e0 = c * 256 + lane * 8;
        uint4 hv = *(const uint4*)(xhi + base + e0);
        uint4 lv = *(const uint4*)(xlo + base + e0);
        __half2* hp = (__half2*)&hv;
        __half2* lp = (__half2*)&lv;
        float a[8] = {0.f, 0.f, 0.f, 0.f, 0.f, 0.f, 0.f, 0.f};
        for (int p = 0; p < nadd; p++) {
            uint4 av4 = *(const uint4*)(addh + (size_t)p * astride + abase + e0);
            __half2* ap = (__half2*)&av4;
            #pragma unroll
            for (int j = 0; j < 4; j++) {
                a[2 * j] += __half2float(ap[j].x);
                a[2 * j + 1] += __half2float(ap[j].y);
            }
        }
        if (cbias) {
            float4 c0 = *(const float4*)(cbias + e0);
            float4 c1 = *(const float4*)(cbias + e0 + 4);
            a[0] += c0.x; a[1] += c0.y; a[2] += c0.z; a[3] += c0.w;
            a[4] += c1.x; a[5] += c1.y; a[6] += c1.z; a[7] += c1.w;
        }
        #pragma unroll
        for (int j = 0; j < 4; j++) {
            v[c * 8 + 2 * j]     = __half2float(hp[j].x) + __half2float(lp[j].x) + a[2 * j];
            v[c * 8 + 2 * j + 1] = __half2float(hp[j].y) + __half2float(lp[j].y) + a[2 * j + 1];
        }
    }
    float s = 0.f;
    #pragma unroll
    for (int i = 0; i < 32; i++) s += v[i];
    float mean = warpSum(s) * (1.f / DD);
    float q = 0.f;
    #pragma unroll
    for (int i = 0; i < 32; i++) {
        float d = v[i] - mean;
        q += d * d;
    }
    float rstd = rsqrtf(warpSum(q) * (1.f / DD) + 1e-5f);
    #pragma unroll
    for (int c = 0; c < 4; c++) {
        int e0 = c * 256 + lane * 8;
        float4 g0 = *(const float4*)(g + e0);
        float4 g1 = *(const float4*)(g + e0 + 4);
        float4 b0 = *(const float4*)(b + e0);
        float4 b1 = *(const float4*)(b + e0 + 4);
        float gg[8] = {g0.x, g0.y, g0.z, g0.w, g1.x, g1.y, g1.z, g1.w};
        float bb[8] = {b0.x, b0.y, b0.z, b0.w, b1.x, b1.y, b1.z, b1.w};
        uint4 ho, lo4;
        __half2* hop = (__half2*)&ho;
        __half2* lop = (__half2*)&lo4;
        #pragma unroll
        for (int j = 0; j < 4; j++) {
            float o0 = (v[c * 8 + 2 * j] - mean) * rstd * gg[2 * j] + bb[2 * j];
            float o1 = (v[c * 8 + 2 * j + 1] - mean) * rstd * gg[2 * j + 1] + bb[2 * j + 1];
            f16 h0, l0, h1, l1;
            f2hl(o0, h0, l0);
            f2hl(o1, h1, l1);
            hop[j] = __halves2half2(h0, h1);
            lop[j] = __halves2half2(l0, l1);
        }
        *(uint4*)(xhi + base + e0) = ho;
        *(uint4*)(xlo + base + e0) = lo4;
    }
}

__global__ __launch_bounds__(256) void pool_mean() {
    int b = blockIdx.y;
    int d = blockIdx.x * 256 + threadIdx.x;
    size_t base = (size_t)b * LL * DD + d;
    float s = 0.f;
    for (int l = 0; l < LL; l++)
        s += __half2float(g_xhi[base + (size_t)l * DD]) +
             __half2float(g_xlo[base + (size_t)l * DD]);
    g_pooled[b * DD + d] = s * (1.f / LL);
}
__global__ __launch_bounds__(256) void logits_kernel(const float* __restrict__ wf,
                                                     const float* __restrict__ bf,
                                                     float* __restrict__ out) {
    int b = blockIdx.x / CC, c = blockIdx.x % CC;
    float s = 0.f;
    for (int d = threadIdx.x; d < DD; d += 256)
        s += g_pooled[b * DD + d] * wf[(size_t)d * CC + c];
    s = blockSum(s);
    if (threadIdx.x == 0) out[b * CC + c] = s + bf[c];
}

extern "C" void kernel_launch(void* const* d_in, const int* in_sizes, int n_in,
                              void* d_out, int out_size) {
    const void*  ids = d_in[0];
    const float* emb = (const float*)d_in[1];
    const float* pe  = (const float*)d_in[2];
    const float* wq  = (const float*)d_in[3];
    const float* bq  = (const float*)d_in[4];
    const float* wk  = (const float*)d_in[5];
    const float* bk  = (const float*)d_in[6];
    const float* wv  = (const float*)d_in[7];
    const float* bv  = (const float*)d_in[8];
    const float* wo  = (const float*)d_in[9];
    const float* bo  = (const float*)d_in[10];
    const float* w1  = (const float*)d_in[11];
    const float* b1  = (const float*)d_in[12];
    const float* w2  = (const float*)d_in[13];
    const float* b2  = (const float*)d_in[14];
    const float* g1  = (const float*)d_in[15];
    const float* be1 = (const float*)d_in[16];
    const float* g2  = (const float*)d_in[17];
    const float* be2 = (const float*)d_in[18];
    const float* wf  = (const float*)d_in[19];
    const float* bf  = (const float*)d_in[20];
    float* out = (float*)d_out;

    const int SM128 = (128 + 128) * PITCH * 5;
    const int SM64  = (64 + 128) * PITCH * 3;
    cudaFuncSetAttribute(gemm_tc<128>, cudaFuncAttributeMaxDynamicSharedMemorySize, SM128);
    cudaFuncSetAttribute(gemm_tc<64>, cudaFuncAttributeMaxDynamicSharedMemorySize, SM64);

    float *bff;
    f16 *xhi, *xlo, *tmph, *qkvp, *qkvh, *ohi, *src2h, *wqkvT, *woT, *WffT, *w1h, *w2T;
    cudaGetSymbolAddress((void**)&bff, g_bff);
    cudaGetSymbolAddress((void**)&xhi, g_xhi);
    cudaGetSymbolAddress((void**)&xlo, g_xlo);
    cudaGetSymbolAddress((void**)&tmph, g_tmph);
    cudaGetSymbolAddress((void**)&qkvp, g_qkvp);
    cudaGetSymbolAddress((void**)&qkvh, g_qkvh);
    cudaGetSymbolAddress((void**)&ohi, g_ohi);
    cudaGetSymbolAddress((void**)&src2h, g_src2h);
    cudaGetSymbolAddress((void**)&wqkvT, g_wqkvT);
    cudaGetSymbolAddress((void**)&woT, g_woT);
    cudaGetSymbolAddress((void**)&WffT, g_WffT);
    cudaGetSymbolAddress((void**)&w1h, g_w1h);
    cudaGetSymbolAddress((void**)&w2T, g_w2T);

    detect_kernel<<<1, 1>>>(ids);
    embed_kernel<<<BB * LL, 256>>>(ids, emb, pe);

    dim3 tb(32, 8);
    tconv4<<<dim3(32, 32, 4), tb>>>(wq, wk, wv, wo);
    tconv<<<dim3(32, 128), tb>>>(w2, w2T, FF, DD);
    conv_h<<<(DD * FF) / 1024, 256>>>(w1, w1h);
    concat_bias<<<3, 1024>>>(bq, bk, bv);
    bff_part<<<32, 256>>>(b1, w2);
    bff_reduce<<<4, 256>>>(b2);
    gemm_tc<64><<<dim3(DD / 128, DD / 64, 1), 128, SM64>>>(w2T, w1h, nullptr,
                                                           nullptr, WffT, FF, FF, DD, 0);

    for (int layer = 0; layer < NLAYER; layer++) {
        // QKV split-K z=2 -> fp16 partials, combined (with bias) by qkv_comb
        gemm_tc<64><<<dim3(3 * DD / 128, LL / 64, 2), 128, SM64>>>(xhi, wqkvT, nullptr,
                                                                   nullptr, qkvp, DD / 2, DD,
                                                                   3 * DD, LL * 3 * DD);
        qkv_comb<<<(LL * 3 * DD) / (256 * 8), 256>>>();
        flash_mma<<<dim3(16, HH), 64>>>(qkvh);
        // O-proj split-K z=4 -> 4 fp16 partials, summed in add_ln
        gemm_tc<64><<<dim3(DD / 128, LL / 64, 4), 128, SM64>>>(ohi, woT, nullptr,
                                                               nullptr, src2h, DD / 4, DD, DD, LL * DD);
        add_ln<<<BB * LL / 8, 256>>>(xhi, xlo, src2h, 4, (size_t)LL * DD, bo,
                                     LL - 1, g1, be1);
        gemm_tc<128><<<dim3(DD / 128, (BB * LL) / 128, 1), 256, SM128>>>(xhi, WffT, bff,
                                                                         nullptr, tmph, DD, DD, DD, 0);
        add_ln<<<BB * LL / 8, 256>>>(xhi, xlo, tmph, 1, 0, nullptr,
                                     BB * LL - 1, g2, be2);
    }

    pool_mean<<<dim3(DD / 256, BB), 256>>>();
    logits_kernel<<<BB * CC, 256>>>(wf, bf, out);
}

// round 17
// speedup vs baseline: 1.0280x; 1.0280x over previous
#include <cuda_runtime.h>
#include <cuda_bf16.h>
#include <cuda_fp16.h>
#include <cstdint>

#define BB 16
#define LL 512
#define DD 1024
#define HH 16
#define FF 4096
#define CC 10
#define NLAYER 6

typedef __half f16;

__device__ f16 g_xhi[BB * LL * DD];
__device__ f16 g_xlo[BB * LL * DD];
__device__ f16 g_tmph[BB * LL * DD];
__device__ f16 g_qkvh[LL * 3 * DD];
__device__ f16 g_ohi[LL * DD];
__device__ f16 g_src2h[2 * LL * DD];
__device__ float g_bff[DD];
__device__ float g_bffpart[32 * DD];
__device__ float g_bqkv[3 * DD];
__device__ float g_pooled[BB * DD];
__device__ int g_ids64;
__device__ f16 g_wqkvT[3 * DD * DD];
__device__ f16 g_woT[DD * DD];
__device__ f16 g_WffT[DD * DD];
__device__ f16 g_w1h[DD * FF];
__device__ f16 g_w2T[DD * FF];

__device__ __forceinline__ void f2hl(float v, f16& h, f16& l) {
    h = __float2half(v);
    l = __float2half(v - __half2float(h));
}
__device__ __forceinline__ float warpSum(float v) {
    #pragma unroll
    for (int o = 16; o > 0; o >>= 1) v += __shfl_xor_sync(0xffffffffu, v, o);
    return v;
}
__device__ __forceinline__ float blockSum(float v) {
    __shared__ float sm[32];
    int lane = threadIdx.x & 31, w = threadIdx.x >> 5;
    v = warpSum(v);
    if (lane == 0) sm[w] = v;
    __syncthreads();
    if (w == 0) {
        float x = (lane < (int)(blockDim.x >> 5)) ? sm[lane] : 0.f;
        x = warpSum(x);
        if (lane == 0) sm[0] = x;
    }
    __syncthreads();
    float r = sm[0];
    __syncthreads();
    return r;
}

__device__ __forceinline__ uint32_t s2u(const void* p) {
    uint32_t a;
    asm("{ .reg .u64 t; cvta.to.shared.u64 t, %1; cvt.u32.u64 %0, t; }" : "=r"(a) : "l"(p));
    return a;
}
__device__ __forceinline__ void cpa(uint32_t dst, const void* src) {
    asm volatile("cp.async.cg.shared.global [%0], [%1], 16;" :: "r"(dst), "l"(src));
}
__device__ __forceinline__ void cpcommit() { asm volatile("cp.async.commit_group;"); }
template <int N> __device__ __forceinline__ void cpwait() {
    asm volatile("cp.async.wait_group %0;" :: "n"(N));
}
__device__ __forceinline__ void ldmx4(uint32_t* r, uint32_t a) {
    asm volatile("ldmatrix.sync.aligned.m8n8.x4.shared.b16 {%0,%1,%2,%3}, [%4];"
                 : "=r"(r[0]), "=r"(r[1]), "=r"(r[2]), "=r"(r[3]) : "r"(a));
}
__device__ __forceinline__ void mmah(float* d, const uint32_t* a, const uint32_t* b) {
    asm volatile(
        "mma.sync.aligned.m16n8k16.row.col.f32.f16.f16.f32 "
        "{%0,%1,%2,%3}, {%4,%5,%6,%7}, {%8,%9}, {%0,%1,%2,%3};"
        : "+f"(d[0]), "+f"(d[1]), "+f"(d[2]), "+f"(d[3])
        : "r"(a[0]), "r"(a[1]), "r"(a[2]), "r"(a[3]), "r"(b[0]), "r"(b[1]));
}

#define PITCH 80

// C[M,N] = A @ B^T + bias ; fp16 operands; multi-stage cp.async, 1 barrier/iter.
template <int MT>
__global__ __launch_bounds__(MT * 2, (MT == 64) ? 4 : 2) void gemm_tc(
    const f16* __restrict__ A, const f16* __restrict__ B,
    const float* __restrict__ bias, float* __restrict__ C, f16* __restrict__ Ch,
    int Kiter, int Kstride, int N, int Czoff) {
    constexpr int THREADS = MT * 2;
    constexpr int OFS_B = MT * PITCH;
    constexpr int STB = (MT + 128) * PITCH;
    constexpr int NST = (MT == 128) ? 5 : 3;
    extern __shared__ char smem[];
    uint32_t sb = s2u(smem);
    const int t = threadIdx.x, lane = t & 31, wid = t >> 5;
    const int m0 = blockIdx.y * MT, n0 = blockIdx.x * 128;
    const int wr = wid >> 2, wc = wid & 3;
    const size_t kz = (size_t)blockIdx.z * Kiter;
    if (C) C += (size_t)blockIdx.z * Czoff;
    if (Ch) Ch += (size_t)blockIdx.z * Czoff;
    const int NKB = Kiter / 32;

    float acc[4][4][4];
    #pragma unroll
    for (int i = 0; i < 4; i++)
        #pragma unroll
        for (int j = 0; j < 4; j++)
            #pragma unroll
            for (int r = 0; r < 4; r++) acc[i][j][r] = 0.f;

    const uint32_t aoff = (uint32_t)((wr * 64 + (lane & 15)) * PITCH + ((lane >> 4) << 4));
    const int brow = wc * 32 + (lane & 7) + ((lane & 16) ? 8 : 0);
    const uint32_t boff = (uint32_t)(brow * PITCH + ((lane & 8) ? 16 : 0));

    auto load_stage = [&](int kb0, uint32_t base) {
        #pragma unroll
        for (int idx = t; idx < MT * 4; idx += THREADS) {
            int row = idx >> 2, c = idx & 3;
            uint32_t so = (uint32_t)(row * PITCH + c * 16);
            cpa(base + so, A + (size_t)(m0 + row) * Kstride + kz + kb0 + c * 8);
        }
        #pragma unroll
        for (int idx = t; idx < 512; idx += THREADS) {
            int row = idx >> 2, c = idx & 3;
            uint32_t so = (uint32_t)(row * PITCH + c * 16);
            cpa(base + OFS_B + so, B + (size_t)(n0 + row) * Kstride + kz + kb0 + c * 8);
        }
        cpcommit();
    };

    #pragma unroll
    for (int s = 0; s < NST - 1; s++)
        load_stage(s * 32, sb + (uint32_t)s * STB);

    for (int kb = 0; kb < NKB; kb++) {
        cpwait<NST - 2>();
        __syncthreads();
        uint32_t base = sb + (uint32_t)(kb % NST) * STB;
        #pragma unroll
        for (int ks = 0; ks < 2; ks++) {
            uint32_t kbyte = (uint32_t)(ks * 32);
            uint32_t ah[4][4], bh[2][4];
            #pragma unroll
            for (int mt = 0; mt < 4; mt++)
                ldmx4(ah[mt], base + aoff + (uint32_t)(mt * 16 * PITCH) + kbyte);
            #pragma unroll
            for (int ng = 0; ng < 2; ng++)
                ldmx4(bh[ng], base + OFS_B + boff + (uint32_t)(ng * 16 * PITCH) + kbyte);
            #pragma unroll
            for (int mt = 0; mt < 4; mt++)
                #pragma unroll
                for (int nt = 0; nt < 4; nt++)
                    mmah(acc[mt][nt], ah[mt], &bh[nt >> 1][(nt & 1) * 2]);
        }
        int nxt = kb + NST - 1;
        if (nxt < NKB)
            load_stage(nxt * 32, sb + (uint32_t)(nxt % NST) * STB);
        else
            cpcommit();
    }

    #pragma unroll
    for (int mt = 0; mt < 4; mt++) {
        int m = m0 + wr * 64 + mt * 16 + (lane >> 2);
        #pragma unroll
        for (int nt = 0; nt < 4; nt++) {
            int n = n0 + wc * 32 + nt * 8 + (lane & 3) * 2;
            float b0 = 0.f, b1 = 0.f;
            if (bias) { b0 = bias[n]; b1 = bias[n + 1]; }
            float v0 = acc[mt][nt][0] + b0, v1 = acc[mt][nt][1] + b1;
            float v2 = acc[mt][nt][2] + b0, v3 = acc[mt][nt][3] + b1;
            if (Ch) {
                *(__half2*)(Ch + (size_t)m * N + n) = __floats2half2_rn(v0, v1);
                *(__half2*)(Ch + (size_t)(m + 8) * N + n) = __floats2half2_rn(v2, v3);
            } else {
                *(float2*)(C + (size_t)m * N + n) = make_float2(v0, v1);
                *(float2*)(C + (size_t)(m + 8) * N + n) = make_float2(v2, v3);
            }
        }
    }
}

__global__ void detect_kernel(const void* ids) {
    const int* p = (const int*)ids;
    int nz = 0;
    for (int i = 0; i < 256; i += 2)
        if (p[i + 1] != 0) nz++;
    g_ids64 = (nz == 0) ? 1 : 0;
}
__global__ void embed_kernel(const void* ids, const float* __restrict__ emb,
                             const float* __restrict__ pe) {
    int row = blockIdx.x;
    int d = threadIdx.x * 4;
    long long id;
    if (g_ids64) id = ((const long long*)ids)[row];
    else         id = (long long)((const int*)ids)[row];
    int l = row & (LL - 1);
    float4 e = *(const float4*)(emb + (size_t)id * DD + d);
    float4 p = *(const float4*)(pe + (size_t)l * DD + d);
    float v[4] = {e.x * 32.f + p.x, e.y * 32.f + p.y, e.z * 32.f + p.z, e.w * 32.f + p.w};
    size_t base = (size_t)row * DD + d;
    #pragma unroll
    for (int j = 0; j < 4; j++) {
        f16 h, lo;
        f2hl(v[j], h, lo);
        g_xhi[base + j] = h;
        g_xlo[base + j] = lo;
    }
}
__global__ void tconv4(const float* __restrict__ wq, const float* __restrict__ wk,
                       const float* __restrict__ wv, const float* __restrict__ wo) {
    __shared__ float tl[32][33];
    int z = blockIdx.z;
    const float* in = (z == 0) ? wq : (z == 1) ? wk : (z == 2) ? wv : wo;
    f16* oh = (z == 3) ? g_woT : g_wqkvT + (size_t)z * DD * DD;
    float scale = (z == 0) ? 0.125f : 1.f;
    int n0 = blockIdx.x * 32, k0 = blockIdx.y * 32;
    int tx = threadIdx.x, ty = threadIdx.y;
    #pragma unroll
    for (int i = 0; i < 4; i++)
        tl[ty + i * 8][tx] = in[(size_t)(k0 + ty + i * 8) * DD + n0 + tx] * scale;
    __syncthreads();
    #pragma unroll
    for (int i = 0; i < 4; i++) {
        int nn = ty + i * 8;
        oh[(size_t)(n0 + nn) * DD + k0 + tx] = __float2half(tl[tx][nn]);
    }
}
__global__ void tconv(const float* __restrict__ in, f16* __restrict__ oh,
                      int R, int C) {
    __shared__ float tl[32][33];
    int n0 = blockIdx.x * 32, k0 = blockIdx.y * 32;
    int tx = threadIdx.x, ty = threadIdx.y;
    #pragma unroll
    for (int i = 0; i < 4; i++)
        tl[ty + i * 8][tx] = in[(size_t)(k0 + ty + i * 8) * C + n0 + tx];
    __syncthreads();
    #pragma unroll
    for (int i = 0; i < 4; i++) {
        int nn = ty + i * 8;
        oh[(size_t)(n0 + nn) * R + k0 + tx] = __float2half(tl[tx][nn]);
    }
}
__global__ void conv_h(const float* __restrict__ in, f16* __restrict__ oh) {
    size_t i = ((size_t)blockIdx.x * 256 + threadIdx.x) * 4;
    float4 v = *(const float4*)(in + i);
    oh[i + 0] = __float2half(v.x);
    oh[i + 1] = __float2half(v.y);
    oh[i + 2] = __float2half(v.z);
    oh[i + 3] = __float2half(v.w);
}
__global__ void concat_bias(const float* __restrict__ bq, const float* __restrict__ bk,
                            const float* __restrict__ bv) {
    int t = threadIdx.x, s = blockIdx.x;
    const float* src = (s == 0) ? bq : (s == 1) ? bk : bv;
    g_bqkv[s * DD + t] = src[t] * ((s == 0) ? 0.125f : 1.f);
}
__global__ __launch_bounds__(256) void bff_part(const float* __restrict__ b1,
                                                const float* __restrict__ w2) {
    int y = blockIdx.x, t = threadIdx.x;
    float s[4] = {0.f, 0.f, 0.f, 0.f};
    for (int f = y * 128; f < y * 128 + 128; f++) {
        float bv = b1[f];
        const float* wr = w2 + (size_t)f * DD;
        #pragma unroll
        for (int j = 0; j < 4; j++) s[j] = fmaf(bv, wr[t + j * 256], s[j]);
    }
    #pragma unroll
    for (int j = 0; j < 4; j++) g_bffpart[y * DD + t + j * 256] = s[j];
}
__global__ __launch_bounds__(256) void bff_reduce(const float* __restrict__ b2) {
    int d = blockIdx.x * 256 + threadIdx.x;
    float s = b2[d];
    for (int y = 0; y < 32; y++) s += g_bffpart[y * DD + d];
    g_bff[d] = s;
}

// ---------------- HMMA flash attention, register-pipelined loads ----------------
__global__ __launch_bounds__(64) void flash_mma(const f16* __restrict__ qkv) {
    __shared__ __align__(16) char fsm[(32 + 64 + 64) * 144];
    const int OFQ = 0, OFK = 32 * 144, OFV = (32 + 64) * 144;
    uint32_t sb = s2u(fsm);
    int h = blockIdx.y, m0 = blockIdx.x * 32;
    int t = threadIdx.x, lane = t & 31, w = t >> 5;

    for (int i = t; i < 256; i += 64) {
        int r = i >> 3, c = i & 7;
        *(uint4*)(fsm + OFQ + r * 144 + c * 16) =
            *(const uint4*)(qkv + (size_t)(m0 + r) * (3 * DD) + h * 64 + c * 8);
    }
    __syncthreads();
    uint32_t qa[4][4];
    {
        uint32_t qoff = (uint32_t)((w * 16 + (lane & 15)) * 144 + ((lane >> 4) << 4));
        #pragma unroll
        for (int kt = 0; kt < 4; kt++) ldmx4(qa[kt], sb + OFQ + qoff + kt * 32);
    }

    const uint32_t brow = (uint32_t)((lane & 7) + ((lane & 16) ? 8 : 0));
    const uint32_t bcol = ((lane & 8) ? 16u : 0u);

    float m_run0 = -1e30f, m_run1 = -1e30f, l_run0 = 0.f, l_run1 = 0.f;
    float oacc[8][4];
    #pragma unroll
    for (int d = 0; d < 8; d++)
        #pragma unroll
        for (int r = 0; r < 4; r++) oacc[d][r] = 0.f;

    uint4 kreg[8];
    __half2 vreg[16][2];
    auto preload = [&](int kb) {
        #pragma unroll
        for (int i = 0; i < 8; i++) {
            int idx = t + i * 64;
            int r = idx >> 3, c = idx & 7;
            kreg[i] = *(const uint4*)(qkv + (size_t)(kb + r) * (3 * DD) + DD + h * 64 + c * 8);
        }
        #pragma unroll
        for (int i = 0; i < 16; i++) {
            int idx = t + i * 64;
            int key2 = (idx >> 5) * 2, d2 = idx & 31;
            const f16* vsrc = qkv + 2 * DD + h * 64 + 2 * d2;
            vreg[i][0] = *(const __half2*)(vsrc + (size_t)(kb + key2) * (3 * DD));
            vreg[i][1] = *(const __half2*)(vsrc + (size_t)(kb + key2 + 1) * (3 * DD));
        }
    };
    preload(0);

    for (int kb = 0; kb < LL; kb += 64) {
        __syncthreads();
        #pragma unroll
        for (int i = 0; i < 8; i++) {
            int idx = t + i * 64;
            int r = idx >> 3, c = idx & 7;
            *(uint4*)(fsm + OFK + r * 144 + c * 16) = kreg[i];
        }
        #pragma unroll
        for (int i = 0; i < 16; i++) {
            int idx = t + i * 64;
            int key2 = (idx >> 5) * 2, d2 = idx & 31;
            __half2 a = vreg[i][0], b = vreg[i][1];
            *(__half2*)(fsm + OFV + (2 * d2) * 144 + key2 * 2) = __halves2half2(a.x, b.x);
            *(__half2*)(fsm + OFV + (2 * d2 + 1) * 144 + key2 * 2) = __halves2half2(a.y, b.y);
        }
        __syncthreads();
        if (kb + 64 < LL) preload(kb + 64);

        float sacc[8][4];
        #pragma unroll
        for (int j = 0; j < 8; j++)
            #pragma unroll
            for (int r = 0; r < 4; r++) sacc[j][r] = 0.f;
        #pragma unroll
        for (int kt = 0; kt < 4; kt++) {
            #pragma unroll
            for (int ng = 0; ng < 4; ng++) {
                uint32_t kbf[4];
                ldmx4(kbf, sb + OFK + (uint32_t)(ng * 16) * 144 + brow * 144 + bcol + kt * 32);
                mmah(sacc[ng * 2 + 0], qa[kt], &kbf[0]);
                mmah(sacc[ng * 2 + 1], qa[kt], &kbf[2]);
            }
        }

        float ml0 = -1e30f, ml1 = -1e30f;
        #pragma unroll
        for (int j = 0; j < 8; j++) {
            ml0 = fmaxf(ml0, fmaxf(sacc[j][0], sacc[j][1]));
            ml1 = fmaxf(ml1, fmaxf(sacc[j][2], sacc[j][3]));
        }
        #pragma unroll
        for (int o = 1; o <= 2; o <<= 1) {
            ml0 = fmaxf(ml0, __shfl_xor_sync(0xffffffffu, ml0, o));
            ml1 = fmaxf(ml1, __shfl_xor_sync(0xffffffffu, ml1, o));
        }
        float mn0 = fmaxf(m_run0, ml0), mn1 = fmaxf(m_run1, ml1);
        float corr0 = __expf(m_run0 - mn0), corr1 = __expf(m_run1 - mn1);
        float rs0 = 0.f, rs1 = 0.f;
        uint32_t pfrag[4][4];
        #pragma unroll
        for (int kt = 0; kt < 4; kt++) {
            #pragma unroll
            for (int hh = 0; hh < 2; hh++) {
                int j = kt * 2 + hh;
                float p0 = __expf(sacc[j][0] - mn0), p1 = __expf(sacc[j][1] - mn0);
                float p2 = __expf(sacc[j][2] - mn1), p3 = __expf(sacc[j][3] - mn1);
                rs0 += p0 + p1;
                rs1 += p2 + p3;
                __half2 pa = __floats2half2_rn(p0, p1);
                __half2 pb = __floats2half2_rn(p2, p3);
                pfrag[kt][hh * 2 + 0] = *(uint32_t*)&pa;
                pfrag[kt][hh * 2 + 1] = *(uint32_t*)&pb;
            }
        }
        #pragma unroll
        for (int o = 1; o <= 2; o <<= 1) {
            rs0 += __shfl_xor_sync(0xffffffffu, rs0, o);
            rs1 += __shfl_xor_sync(0xffffffffu, rs1, o);
        }
        l_run0 = l_run0 * corr0 + rs0;
        l_run1 = l_run1 * corr1 + rs1;
        m_run0 = mn0;
        m_run1 = mn1;
        #pragma unroll
        for (int d = 0; d < 8; d++) {
            oacc[d][0] *= corr0; oacc[d][1] *= corr0;
            oacc[d][2] *= corr1; oacc[d][3] *= corr1;
        }
        #pragma unroll
        for (int kt = 0; kt < 4; kt++) {
            #pragma unroll
            for (int ng = 0; ng < 4; ng++) {
                uint32_t vb[4];
                ldmx4(vb, sb + OFV + (uint32_t)(ng * 16) * 144 + brow * 144 + bcol + kt * 32);
                mmah(oacc[ng * 2 + 0], pfrag[kt], &vb[0]);
                mmah(oacc[ng * 2 + 1], pfrag[kt], &vb[2]);
            }
        }
    }

    float inv0 = 1.f / l_run0, inv1 = 1.f / l_run1;
    int m = m0 + w * 16 + (lane >> 2);
    #pragma unroll
    for (int d = 0; d < 8; d++) {
        int n = h * 64 + d * 8 + 2 * (lane & 3);
        *(__half2*)(g_ohi + (size_t)m * DD + n) = __floats2half2_rn(oacc[d][0] * inv0, oacc[d][1] * inv0);
        *(__half2*)(g_ohi + (size_t)(m + 8) * DD + n) = __floats2half2_rn(oacc[d][2] * inv1, oacc[d][3] * inv1);
    }
}

// ---------------- warp-per-row residual + LayerNorm (two-pass) ----------------
__global__ __launch_bounds__(256) void add_ln(f16* __restrict__ xhi, f16* __restrict__ xlo,
                                              const f16* __restrict__ addh,
                                              const f16* __restrict__ addh2,
                                              const float* __restrict__ cbias, int addMask,
                                              const float* __restrict__ g,
                                              const float* __restrict__ b) {
    int row = blockIdx.x * 8 + (threadIdx.x >> 5);
    int lane = threadIdx.x & 31;
    size_t base = (size_t)row * DD;
    size_t abase = (size_t)(row & addMask) * DD;
    float v[32];
    #pragma unroll
    for (int c = 0; c < 4; c++) {
        int e0 = c * 256 + lane * 8;
        uint4 hv = *(const uint4*)(xhi + base + e0);
        uint4 lv = *(const uint4*)(xlo + base + e0);
        __half2* hp = (__half2*)&hv;
        __half2* lp = (__half2*)&lv;
        float a[8];
        uint4 av4 = *(const uint4*)(addh + abase + e0);
        __half2* ap = (__half2*)&av4;
        #pragma unroll
        for (int j = 0; j < 4; j++) {
            a[2 * j] = __half2float(ap[j].x);
            a[2 * j + 1] = __half2float(ap[j].y);
        }
        if (addh2) {
            uint4 a2 = *(const uint4*)(addh2 + abase + e0);
            __half2* a2p = (__half2*)&a2;
            #pragma unroll
            for (int j = 0; j < 4; j++) {
                a[2 * j] += __half2float(a2p[j].x);
                a[2 * j + 1] += __half2float(a2p[j].y);
            }
        }
        if (cbias) {
            float4 c0 = *(const float4*)(cbias + e0);
            float4 c1 = *(const float4*)(cbias + e0 + 4);
            a[0] += c0.x; a[1] += c0.y; a[2] += c0.z; a[3] += c0.w;
            a[4] += c1.x; a[5] += c1.y; a[6] += c1.z; a[7] += c1.w;
        }
        #pragma unroll
        for (int j = 0; j < 4; j++) {
            v[c * 8 + 2 * j]     = __half2float(hp[j].x) + __half2float(lp[j].x) + a[2 * j];
            v[c * 8 + 2 * j + 1] = __half2float(hp[j].y) + __half2float(lp[j].y) + a[2 * j + 1];
        }
    }
    float s = 0.f;
    #pragma unroll
    for (int i = 0; i < 32; i++) s += v[i];
    float mean = warpSum(s) * (1.f / DD);
    float q = 0.f;
    #pragma unroll
    for (int i = 0; i < 32; i++) {
        float d = v[i] - mean;
        q += d * d;
    }
    float rstd = rsqrtf(warpSum(q) * (1.f / DD) + 1e-5f);
    #pragma unroll
    for (int c = 0; c < 4; c++) {
        int e0 = c * 256 + lane * 8;
        float4 g0 = *(const float4*)(g + e0);
        float4 g1 = *(const float4*)(g + e0 + 4);
        float4 b0 = *(const float4*)(b + e0);
        float4 b1 = *(const float4*)(b + e0 + 4);
        float gg[8] = {g0.x, g0.y, g0.z, g0.w, g1.x, g1.y, g1.z, g1.w};
        float bb[8] = {b0.x, b0.y, b0.z, b0.w, b1.x, b1.y, b1.z, b1.w};
        uint4 ho, lo4;
        __half2* hop = (__half2*)&ho;
        __half2* lop = (__half2*)&lo4;
        #pragma unroll
        for (int j = 0; j < 4; j++) {
            float o0 = (v[c * 8 + 2 * j] - mean) * rstd * gg[2 * j] + bb[2 * j];
            float o1 = (v[c * 8 + 2 * j + 1] - mean) * rstd * gg[2 * j + 1] + bb[2 * j + 1];
            f16 h0, l0, h1, l1;
            f2hl(o0, h0, l0);
            f2hl(o1, h1, l1);
            hop[j] = __halves2half2(h0, h1);
            lop[j] = __halves2half2(l0, l1);
        }
        *(uint4*)(xhi + base + e0) = ho;
        *(uint4*)(xlo + base + e0) = lo4;
    }
}

__global__ __launch_bounds__(256) void pool_mean() {
    int b = blockIdx.y;
    int d2 = (blockIdx.x * 256 + threadIdx.x) * 2;
    size_t base = (size_t)b * LL * DD + d2;
    float s0 = 0.f, s1 = 0.f;
    for (int l = 0; l < LL; l++) {
        __half2 h = *(const __half2*)(g_xhi + base + (size_t)l * DD);
        __half2 lo = *(const __half2*)(g_xlo + base + (size_t)l * DD);
        s0 += __half2float(h.x) + __half2float(lo.x);
        s1 += __half2float(h.y) + __half2float(lo.y);
    }
    g_pooled[b * DD + d2] = s0 * (1.f / LL);
    g_pooled[b * DD + d2 + 1] = s1 * (1.f / LL);
}
__global__ __launch_bounds__(256) void logits_kernel(const float* __restrict__ wf,
                                                     const float* __restrict__ bf,
                                                     float* __restrict__ out) {
    int b = blockIdx.x / CC, c = blockIdx.x % CC;
    float s = 0.f;
    for (int d = threadIdx.x; d < DD; d += 256)
        s += g_pooled[b * DD + d] * wf[(size_t)d * CC + c];
    s = blockSum(s);
    if (threadIdx.x == 0) out[b * CC + c] = s + bf[c];
}

extern "C" void kernel_launch(void* const* d_in, const int* in_sizes, int n_in,
                              void* d_out, int out_size) {
    const void*  ids = d_in[0];
    const float* emb = (const float*)d_in[1];
    const float* pe  = (const float*)d_in[2];
    const float* wq  = (const float*)d_in[3];
    const float* bq  = (const float*)d_in[4];
    const float* wk  = (const float*)d_in[5];
    const float* bk  = (const float*)d_in[6];
    const float* wv  = (const float*)d_in[7];
    const float* bv  = (const float*)d_in[8];
    const float* wo  = (const float*)d_in[9];
    const float* bo  = (const float*)d_in[10];
    const float* w1  = (const float*)d_in[11];
    const float* b1  = (const float*)d_in[12];
    const float* w2  = (const float*)d_in[13];
    const float* b2  = (const float*)d_in[14];
    const float* g1  = (const float*)d_in[15];
    const float* be1 = (const float*)d_in[16];
    const float* g2  = (const float*)d_in[17];
    const float* be2 = (const float*)d_in[18];
    const float* wf  = (const float*)d_in[19];
    const float* bf  = (const float*)d_in[20];
    float* out = (float*)d_out;

    const int SM128 = (128 + 128) * PITCH * 5;
    const int SM64  = (64 + 128) * PITCH * 3;
    cudaFuncSetAttribute(gemm_tc<128>, cudaFuncAttributeMaxDynamicSharedMemorySize, SM128);
    cudaFuncSetAttribute(gemm_tc<64>, cudaFuncAttributeMaxDynamicSharedMemorySize, SM64);

    float *bff, *bqkv;
    f16 *xhi, *xlo, *tmph, *qkvh, *ohi, *src2h, *wqkvT, *woT, *WffT, *w1h, *w2T;
    cudaGetSymbolAddress((void**)&bff, g_bff);
    cudaGetSymbolAddress((void**)&bqkv, g_bqkv);
    cudaGetSymbolAddress((void**)&xhi, g_xhi);
    cudaGetSymbolAddress((void**)&xlo, g_xlo);
    cudaGetSymbolAddress((void**)&tmph, g_tmph);
    cudaGetSymbolAddress((void**)&qkvh, g_qkvh);
    cudaGetSymbolAddress((void**)&ohi, g_ohi);
    cudaGetSymbolAddress((void**)&src2h, g_src2h);
    cudaGetSymbolAddress((void**)&wqkvT, g_wqkvT);
    cudaGetSymbolAddress((void**)&woT, g_woT);
    cudaGetSymbolAddress((void**)&WffT, g_WffT);
    cudaGetSymbolAddress((void**)&w1h, g_w1h);
    cudaGetSymbolAddress((void**)&w2T, g_w2T);

    detect_kernel<<<1, 1>>>(ids);
    embed_kernel<<<BB * LL, 256>>>(ids, emb, pe);

    dim3 tb(32, 8);
    tconv4<<<dim3(32, 32, 4), tb>>>(wq, wk, wv, wo);
    tconv<<<dim3(32, 128), tb>>>(w2, w2T, FF, DD);
    conv_h<<<(DD * FF) / 1024, 256>>>(w1, w1h);
    concat_bias<<<3, 1024>>>(bq, bk, bv);
    bff_part<<<32, 256>>>(b1, w2);
    bff_reduce<<<4, 256>>>(b2);
    gemm_tc<64><<<dim3(DD / 128, DD / 64, 1), 128, SM64>>>(w2T, w1h, nullptr,
                                                           nullptr, WffT, FF, FF, DD, 0);

    for (int layer = 0; layer < NLAYER; layer++) {
        gemm_tc<64><<<dim3(3 * DD / 128, LL / 64, 1), 128, SM64>>>(xhi, wqkvT, bqkv,
                                                                   nullptr, qkvh, DD, DD, 3 * DD, 0);
        flash_mma<<<dim3(16, HH), 64>>>(qkvh);
        gemm_tc<64><<<dim3(DD / 128, LL / 64, 2), 128, SM64>>>(ohi, woT, nullptr,
                                                               nullptr, src2h, DD / 2, DD, DD, LL * DD);
        add_ln<<<BB * LL / 8, 256>>>(xhi, xlo, src2h, src2h + (size_t)LL * DD, bo,
                                     LL - 1, g1, be1);
        gemm_tc<128><<<dim3(DD / 128, (BB * LL) / 128, 1), 256, SM128>>>(xhi, WffT, bff,
                                                                         nullptr, tmph, DD, DD, DD, 0);
        add_ln<<<BB * LL / 8, 256>>>(xhi, xlo, tmph, nullptr, nullptr,
                                     BB * LL - 1, g2, be2);
    }

    pool_mean<<<dim3(DD / 512, BB), 256>>>();
    logits_kernel<<<BB * CC, 256>>>(wf, bf, out);
}